// round 8
// baseline (speedup 1.0000x reference)
#include <cuda_runtime.h>
#include <cstdint>

#define MAXB 262144
__device__ float g_state[(size_t)MAXB * 64];

typedef unsigned long long u64t;

// ---- duplicated-weight scratch: each weight w stored as packed (w,w) u64 ----
#define OFF_CARD 0
#define OFF_LP   26624        // 416*64
#define OFF_SN   29952        // +52*64
#define OFF_SP   33280        // +52*64
#define OFF_WV1  47616        // +224*64
#define OFF_WA1  51712        // +64*64
#define OFF_WA2  55104        // +53*64
#define OFF_WP1  59200        // +64*64
#define NDUP     67392        // +128*64
__device__ u64t g_wdup[NDUP];

__device__ __forceinline__ u64t pk2(float lo, float hi) {
    u64t r; asm("mov.b64 %0, {%1, %2};" : "=l"(r) : "f"(lo), "f"(hi)); return r;
}
__device__ __forceinline__ void upk2(u64t p, float& lo, float& hi) {
    asm("mov.b64 {%0, %1}, %2;" : "=f"(lo), "=f"(hi) : "l"(p));
}
__device__ __forceinline__ void ffma2(u64t& d, u64t a, u64t b) {
    asm("fma.rn.f32x2 %0, %1, %2, %0;" : "+l"(d) : "l"(a), "l"(b));
}

// ===================== prep: duplicate weights =====================
__global__ void prep_kernel(const float* __restrict__ Wc, const float* __restrict__ Wlp,
                            const float* __restrict__ Wsn, const float* __restrict__ Wsp,
                            const float* __restrict__ Wv1, const float* __restrict__ Wa1,
                            const float* __restrict__ Wa2, const float* __restrict__ Wp1) {
    int i = blockIdx.x * 256 + threadIdx.x;
    if (i >= NDUP) return;
    float w;
    if      (i < OFF_LP)  w = __ldg(Wc  + i);
    else if (i < OFF_SN)  w = __ldg(Wlp + (i - OFF_LP));
    else if (i < OFF_SP)  w = __ldg(Wsn + (i - OFF_SN));
    else if (i < OFF_WV1) w = __ldg(Wsp + (i - OFF_SP));
    else if (i < OFF_WA1) w = __ldg(Wv1 + (i - OFF_WV1));
    else if (i < OFF_WA2) w = __ldg(Wa1 + (i - OFF_WA1));
    else if (i < OFF_WP1) w = __ldg(Wa2 + (i - OFF_WA2));
    else                  w = __ldg(Wp1 + (i - OFF_WP1));
    g_wdup[i] = pk2(w, w);
}

#define NA      64    // tile rows
#define LDA     68    // smem row stride (floats)
#define THREADS 512   // 16 warps: warp -> 4 outputs, lane -> 2 rows

// acc[o]: packed pair over this lane's 2 rows for output og4+o
__device__ __forceinline__ void acc_init(u64t (&acc)[4], const float* __restrict__ bias, int og4) {
#pragma unroll
    for (int o = 0; o < 4; o++) {
        float b = __ldg(bias + og4 + o);
        acc[o] = pk2(b, b);
    }
}

// OUT[64 rows][64 outs] += A_sm(k-major [K][64])^T @ Wdup([K][64] as (w,w) u64)
__device__ __forceinline__ void gemm_k(u64t (&acc)[4], const float* __restrict__ As,
                                       const u64t* __restrict__ Dw, int K,
                                       int lane2, int og4) {
#pragma unroll 4
    for (int k = 0; k < K; k++) {
        u64t a = *reinterpret_cast<const u64t*>(As + k * LDA + lane2);
        const ulonglong2* wp = reinterpret_cast<const ulonglong2*>(Dw + (size_t)k * 64 + og4);
        ulonglong2 w0 = __ldg(wp);
        ulonglong2 w1 = __ldg(wp + 1);
        ffma2(acc[0], a, w0.x); ffma2(acc[1], a, w0.y);
        ffma2(acc[2], a, w1.x); ffma2(acc[3], a, w1.y);
    }
}

__device__ __forceinline__ void relu_store(u64t (&acc)[4], float* __restrict__ Ot,
                                           int lane2, int og4) {
#pragma unroll
    for (int o = 0; o < 4; o++) {
        float x0, x1; upk2(acc[o], x0, x1);
        *reinterpret_cast<float2*>(Ot + (og4 + o) * LDA + lane2) =
            make_float2(fmaxf(x0, 0.f), fmaxf(x1, 0.f));
    }
}

// ===================== Kernel A: state encoder + values =====================
__global__ void __launch_bounds__(THREADS, 2) state_kernel(
    const int*   __restrict__ hand_ids,
    const float* __restrict__ dense_state,
    const float* __restrict__ emb_table,
    const float* __restrict__ ln1_g, const float* __restrict__ ln1_b,
    const float* __restrict__ b_card, const float* __restrict__ b_lp,
    const float* __restrict__ b_sn,
    const float* __restrict__ W_ct,   const float* __restrict__ b_ct,
    const float* __restrict__ b_sp,
    const float* __restrict__ ln2_g,  const float* __restrict__ ln2_b,
    const float* __restrict__ bv1,
    const float* __restrict__ Wv2,    const float* __restrict__ bv2,
    float* __restrict__ out_values,
    int B)
{
    __shared__ float Dbuf[52 * LDA];   // dense slice, k-major
    __shared__ float Xb[64 * LDA];     // activation buffer, k-major
    __shared__ float lnet[32 * 56];    // LN'd emb transposed [dim][id]
    __shared__ float ctb[3 * LDA];
    __shared__ float Sbuf[NA], S2buf[NA], Rbuf[NA];
    __shared__ int   sid[NA * 13];

    int tid = threadIdx.x;
    int lane2 = (tid & 31) * 2;
    int og4 = (tid >> 5) * 4;
    long long s0 = (long long)blockIdx.x * NA;
    int ns = (int)(((long long)B - s0) < NA ? ((long long)B - s0) : NA);

    // ---- staging ----
    for (int i = tid; i < ns * 13; i += THREADS) sid[i] = __ldg(hand_ids + s0 * 13 + i);
    for (int i = tid; i < ns * 52; i += THREADS) {       // lp slice rows 0..51
        int s = i / 52, f = i - s * 52;
        Dbuf[f * LDA + s] = __ldg(dense_state + (s0 + s) * 107 + f);
    }
    if (tid < 53) {
        const float4* e4 = reinterpret_cast<const float4*>(emb_table + tid * 32);
        float vals[32]; float s = 0.f, s2 = 0.f;
#pragma unroll
        for (int k = 0; k < 8; k++) {
            float4 f = __ldg(e4 + k);
            vals[4*k] = f.x; vals[4*k+1] = f.y; vals[4*k+2] = f.z; vals[4*k+3] = f.w;
            s += f.x + f.y + f.z + f.w;
            s2 += f.x*f.x + f.y*f.y + f.z*f.z + f.w*f.w;
        }
        float m = s * (1.f/32.f);
        float rv = rsqrtf(s2 * (1.f/32.f) - m*m + 1e-5f);
#pragma unroll
        for (int d = 0; d < 32; d++)
            lnet[d * 56 + tid] = (vals[d] - m) * rv * __ldg(ln1_g + d) + __ldg(ln1_b + d);
    }
    if (tid < NA) { Sbuf[tid] = 0.f; S2buf[tid] = 0.f; Rbuf[tid] = 0.f; }
    __syncthreads();

    // ---- card layer: 13 chunks of K=32 ----
    u64t cacc[4];
    acc_init(cacc, b_card, og4);
    for (int c = 0; c < 13; c++) {
        {   // build chunk: Xb[k][s] = lnemb[k][ id(s,c) ]
            int k = tid >> 4, sb = (tid & 15) * 4;
#pragma unroll
            for (int i = 0; i < 4; i++) {
                int s = sb + i;
                int id = sid[s * 13 + c];
                if ((unsigned)id > 52u) id = 52;
                Xb[k * LDA + s] = lnet[k * 56 + id];
            }
        }
        __syncthreads();
        gemm_k(cacc, Xb, g_wdup + OFF_CARD + (size_t)(c * 32) * 64, 32, lane2, og4);
        __syncthreads();
    }
    relu_store(cacc, Xb, lane2, og4);        // e -> Xb
    __syncthreads();

    // ---- sp accumulates in registers across 4 passes ----
    u64t spacc[4];
    acc_init(spacc, b_sp, og4);
    gemm_k(spacc, Xb, g_wdup + OFF_SP, 64, lane2, og4);          // pass1: e

    u64t acc[4];
    acc_init(acc, b_lp, og4);
    gemm_k(acc, Dbuf, g_wdup + OFF_LP, 52, lane2, og4);          // lp
    __syncthreads();
    relu_store(acc, Xb, lane2, og4);                             // lp -> Xb
    // restage Dbuf with sn rows 52..103, ctb with 104..106
    for (int i = tid; i < ns * 52; i += THREADS) {
        int s = i / 52, f = i - s * 52;
        Dbuf[f * LDA + s] = __ldg(dense_state + (s0 + s) * 107 + 52 + f);
    }
    for (int i = tid; i < ns * 3; i += THREADS) {
        int f = i / NA, s = i - f * NA;
        ctb[f * LDA + s] = __ldg(dense_state + (s0 + s) * 107 + 104 + f);
    }
    __syncthreads();
    gemm_k(spacc, Xb, g_wdup + OFF_SP + 64 * 64, 64, lane2, og4); // pass2: lp
    acc_init(acc, b_sn, og4);
    gemm_k(acc, Dbuf, g_wdup + OFF_SN, 52, lane2, og4);           // sn
    __syncthreads();
    relu_store(acc, Xb, lane2, og4);
    __syncthreads();
    gemm_k(spacc, Xb, g_wdup + OFF_SP + 128 * 64, 64, lane2, og4); // pass3: sn
    __syncthreads();
    {   // ct (3->32) direct into Xb rows 0..31
        int j = tid >> 4, sb = (tid & 15) * 4;
        float w0 = __ldg(W_ct + j), w1 = __ldg(W_ct + 32 + j), w2 = __ldg(W_ct + 64 + j);
        float bj = __ldg(b_ct + j);
#pragma unroll
        for (int i = 0; i < 4; i++) {
            int s = sb + i;
            float v = bj + ctb[s] * w0 + ctb[LDA + s] * w1 + ctb[2 * LDA + s] * w2;
            Xb[j * LDA + s] = fmaxf(v, 0.f);
        }
    }
    __syncthreads();
    gemm_k(spacc, Xb, g_wdup + OFF_SP + 192 * 64, 32, lane2, og4); // pass4: ct

    // ---- relu + LayerNorm (cross-warp smem atomics) ----
    float hv[2][4];
#pragma unroll
    for (int o = 0; o < 4; o++) {
        float x0, x1; upk2(spacc[o], x0, x1);
        hv[0][o] = fmaxf(x0, 0.f); hv[1][o] = fmaxf(x1, 0.f);
    }
#pragma unroll
    for (int c = 0; c < 2; c++) {
        float s = hv[c][0] + hv[c][1] + hv[c][2] + hv[c][3];
        float s2 = hv[c][0]*hv[c][0] + hv[c][1]*hv[c][1] + hv[c][2]*hv[c][2] + hv[c][3]*hv[c][3];
        atomicAdd(&Sbuf[lane2 + c], s);
        atomicAdd(&S2buf[lane2 + c], s2);
    }
    __syncthreads();
    {
        float g[4], be[4];
#pragma unroll
        for (int o = 0; o < 4; o++) { g[o] = __ldg(ln2_g + og4 + o); be[o] = __ldg(ln2_b + og4 + o); }
#pragma unroll
        for (int c = 0; c < 2; c++) {
            float m = Sbuf[lane2 + c] * (1.f/64.f);
            float rv = rsqrtf(S2buf[lane2 + c] * (1.f/64.f) - m * m + 1e-5f);
#pragma unroll
            for (int o = 0; o < 4; o++) hv[c][o] = (hv[c][o] - m) * rv * g[o] + be[o];
        }
#pragma unroll
        for (int o = 0; o < 4; o++)
            *reinterpret_cast<float2*>(Xb + (og4 + o) * LDA + lane2) =
                make_float2(hv[0][o], hv[1][o]);
    }
    __syncthreads();

    {   // write state_h coalesced from Xb
        int tl = tid >> 3, q = tid & 7;
        if (tl < ns) {
            float v[8];
#pragma unroll
            for (int j = 0; j < 8; j++) v[j] = Xb[(q * 8 + j) * LDA + tl];
            float4* dst4 = reinterpret_cast<float4*>(g_state + (s0 + tl) * 64 + q * 8);
            dst4[0] = make_float4(v[0], v[1], v[2], v[3]);
            dst4[1] = make_float4(v[4], v[5], v[6], v[7]);
        }
    }

    // ---- value head ----
    acc_init(acc, bv1, og4);
    gemm_k(acc, Xb, g_wdup + OFF_WV1, 64, lane2, og4);
    {
        float p0 = 0.f, p1 = 0.f;
#pragma unroll
        for (int o = 0; o < 4; o++) {
            float w = __ldg(Wv2 + og4 + o);
            float x0, x1; upk2(acc[o], x0, x1);
            p0 = fmaf(fmaxf(x0, 0.f), w, p0);
            p1 = fmaf(fmaxf(x1, 0.f), w, p1);
        }
        atomicAdd(&Rbuf[lane2 + 0], p0);
        atomicAdd(&Rbuf[lane2 + 1], p1);
    }
    __syncthreads();
    if (tid < ns) out_values[s0 + tid] = Rbuf[tid] + __ldg(bv2);
}

// ===================== Kernel B: action encoder + logits =====================
__global__ void __launch_bounds__(THREADS, 2) action_kernel(
    const float* __restrict__ action_feats,
    const int*   __restrict__ segment_ids,
    const float* __restrict__ ba1, const float* __restrict__ ba2,
    const float* __restrict__ bp1,
    const float* __restrict__ Wp2, const float* __restrict__ bp2,
    float* __restrict__ out_logits,
    int T)
{
    __shared__ float buf1[64 * LDA];   // AFt, later aenc
    __shared__ float buf2[64 * LDA];   // a1, later gathered state
    __shared__ float Rbuf[NA];

    int tid = threadIdx.x;
    int lane2 = (tid & 31) * 2;
    int og4 = (tid >> 5) * 4;
    long long base = (long long)blockIdx.x * NA;
    int nt = (int)(((long long)T - base) < NA ? ((long long)T - base) : NA);

    for (int i = tid; i < nt * 53; i += THREADS) {
        int t = i / 53, f = i - t * 53;
        buf1[f * LDA + t] = __ldg(action_feats + (base + t) * 53 + f);
    }
    if (tid < NA) Rbuf[tid] = 0.f;
    __syncthreads();

    u64t acc[4];
    acc_init(acc, ba1, og4);
    gemm_k(acc, buf1, g_wdup + OFF_WA1, 53, lane2, og4);
    relu_store(acc, buf2, lane2, og4);          // a1 -> buf2
    __syncthreads();

    acc_init(acc, ba2, og4);
    gemm_k(acc, buf2, g_wdup + OFF_WA2, 64, lane2, og4);
    __syncthreads();                            // all warps done reading buf2
    relu_store(acc, buf1, lane2, og4);          // aenc -> buf1
    {   // gather state rows into buf2 (k-major)
        int tl = tid >> 3, q = tid & 7;
        if (tl < nt) {
            int seg = __ldg(segment_ids + base + tl);
            const float4* gs = reinterpret_cast<const float4*>(g_state + (size_t)seg * 64 + q * 8);
            float4 f0 = __ldg(gs), f1 = __ldg(gs + 1);
            int k0 = q * 8;
            buf2[(k0 + 0) * LDA + tl] = f0.x; buf2[(k0 + 1) * LDA + tl] = f0.y;
            buf2[(k0 + 2) * LDA + tl] = f0.z; buf2[(k0 + 3) * LDA + tl] = f0.w;
            buf2[(k0 + 4) * LDA + tl] = f1.x; buf2[(k0 + 5) * LDA + tl] = f1.y;
            buf2[(k0 + 6) * LDA + tl] = f1.z; buf2[(k0 + 7) * LDA + tl] = f1.w;
        }
    }
    __syncthreads();

    acc_init(acc, bp1, og4);
    gemm_k(acc, buf2, g_wdup + OFF_WP1, 64, lane2, og4);           // state part
    gemm_k(acc, buf1, g_wdup + OFF_WP1 + 64 * 64, 64, lane2, og4); // aenc part
    {
        float p0 = 0.f, p1 = 0.f;
#pragma unroll
        for (int o = 0; o < 4; o++) {
            float w = __ldg(Wp2 + og4 + o);
            float x0, x1; upk2(acc[o], x0, x1);
            p0 = fmaf(fmaxf(x0, 0.f), w, p0);
            p1 = fmaf(fmaxf(x1, 0.f), w, p1);
        }
        atomicAdd(&Rbuf[lane2 + 0], p0);
        atomicAdd(&Rbuf[lane2 + 1], p1);
    }
    __syncthreads();
    if (tid < nt) out_logits[base + tid] = Rbuf[tid] + __ldg(bp2);
}

// ===================== launch =====================
extern "C" void kernel_launch(void* const* d_in, const int* in_sizes, int n_in,
                              void* d_out, int out_size) {
    const int*   hand_ids     = (const int*)  d_in[0];
    const float* dense_state  = (const float*)d_in[1];
    const float* action_feats = (const float*)d_in[2];
    const int*   segment_ids  = (const int*)  d_in[3];
    const float* emb_table    = (const float*)d_in[4];
    const float* ln1_g        = (const float*)d_in[5];
    const float* ln1_b        = (const float*)d_in[6];
    const float* W_card       = (const float*)d_in[7];
    const float* b_card       = (const float*)d_in[8];
    const float* W_lp         = (const float*)d_in[9];
    const float* b_lp         = (const float*)d_in[10];
    const float* W_sn         = (const float*)d_in[11];
    const float* b_sn         = (const float*)d_in[12];
    const float* W_ct         = (const float*)d_in[13];
    const float* b_ct         = (const float*)d_in[14];
    const float* W_sp         = (const float*)d_in[15];
    const float* b_sp         = (const float*)d_in[16];
    const float* ln2_g        = (const float*)d_in[17];
    const float* ln2_b        = (const float*)d_in[18];
    const float* Wa1          = (const float*)d_in[19];
    const float* ba1          = (const float*)d_in[20];
    const float* Wa2          = (const float*)d_in[21];
    const float* ba2          = (const float*)d_in[22];
    const float* Wp1          = (const float*)d_in[23];
    const float* bp1          = (const float*)d_in[24];
    const float* Wp2          = (const float*)d_in[25];
    const float* bp2          = (const float*)d_in[26];
    const float* Wv1          = (const float*)d_in[27];
    const float* bv1          = (const float*)d_in[28];
    const float* Wv2          = (const float*)d_in[29];
    const float* bv2          = (const float*)d_in[30];

    int B = in_sizes[0] / 13;
    int T = in_sizes[3];
    float* out = (float*)d_out;   // layout: logits[T] then values[B]

    prep_kernel<<<(NDUP + 255) / 256, 256>>>(W_card, W_lp, W_sn, W_sp, Wv1, Wa1, Wa2, Wp1);

    state_kernel<<<(B + NA - 1) / NA, THREADS>>>(
        hand_ids, dense_state, emb_table, ln1_g, ln1_b,
        b_card, b_lp, b_sn, W_ct, b_ct, b_sp, ln2_g, ln2_b,
        bv1, Wv2, bv2, out + (size_t)T, B);

    action_kernel<<<(T + NA - 1) / NA, THREADS>>>(
        action_feats, segment_ids, ba1, ba2, bp1, Wp2, bp2, out, T);
}

// round 11
// speedup vs baseline: 1.0332x; 1.0332x over previous
#include <cuda_runtime.h>
#include <cstdint>

#define MAXB 262144
__device__ float g_state[(size_t)MAXB * 64];

typedef unsigned long long u64t;

// ---- duplicated-weight scratch: each weight w stored as packed (w,w) u64 ----
#define OFF_CARD 0
#define OFF_LP   26624        // 416*64
#define OFF_SN   29952        // +52*64
#define OFF_SP   33280        // +52*64
#define OFF_WV1  47616        // +224*64
#define OFF_WA1  51712        // +64*64
#define OFF_WA2  55104        // +53*64
#define OFF_WP1  59200        // +64*64
#define NDUP     67392        // +128*64
__device__ u64t g_wdup[NDUP];

__device__ __forceinline__ u64t pk2(float lo, float hi) {
    u64t r; asm("mov.b64 %0, {%1, %2};" : "=l"(r) : "f"(lo), "f"(hi)); return r;
}
__device__ __forceinline__ void upk2(u64t p, float& lo, float& hi) {
    asm("mov.b64 {%0, %1}, %2;" : "=f"(lo), "=f"(hi) : "l"(p));
}
__device__ __forceinline__ void ffma2(u64t& d, u64t a, u64t b) {
    asm("fma.rn.f32x2 %0, %1, %2, %0;" : "+l"(d) : "l"(a), "l"(b));
}

// ===================== prep: duplicate weights =====================
__global__ void prep_kernel(const float* __restrict__ Wc, const float* __restrict__ Wlp,
                            const float* __restrict__ Wsn, const float* __restrict__ Wsp,
                            const float* __restrict__ Wv1, const float* __restrict__ Wa1,
                            const float* __restrict__ Wa2, const float* __restrict__ Wp1) {
    int i = blockIdx.x * 256 + threadIdx.x;
    if (i >= NDUP) return;
    float w;
    if      (i < OFF_LP)  w = __ldg(Wc  + i);
    else if (i < OFF_SN)  w = __ldg(Wlp + (i - OFF_LP));
    else if (i < OFF_SP)  w = __ldg(Wsn + (i - OFF_SN));
    else if (i < OFF_WV1) w = __ldg(Wsp + (i - OFF_SP));
    else if (i < OFF_WA1) w = __ldg(Wv1 + (i - OFF_WV1));
    else if (i < OFF_WA2) w = __ldg(Wa1 + (i - OFF_WA1));
    else if (i < OFF_WP1) w = __ldg(Wa2 + (i - OFF_WA2));
    else                  w = __ldg(Wp1 + (i - OFF_WP1));
    g_wdup[i] = pk2(w, w);
}

#define NA      64    // tile rows
#define LDA     68    // smem row stride (floats)
#define THREADS 512   // 16 warps: warp -> 4 outputs, lane -> 2 rows

// acc[o]: packed pair over this lane's 2 rows for output og4+o
__device__ __forceinline__ void acc_init(u64t (&acc)[4], const float* __restrict__ bias, int og4) {
#pragma unroll
    for (int o = 0; o < 4; o++) {
        float b = __ldg(bias + og4 + o);
        acc[o] = pk2(b, b);
    }
}

// OUT[64 rows][64 outs] += A_sm(k-major [K][64])^T @ Wdup([K][64] as (w,w) u64)
__device__ __forceinline__ void gemm_k(u64t (&acc)[4], const float* __restrict__ As,
                                       const u64t* __restrict__ Dw, int K,
                                       int lane2, int og4) {
#pragma unroll 4
    for (int k = 0; k < K; k++) {
        u64t a = *reinterpret_cast<const u64t*>(As + k * LDA + lane2);
        const ulonglong2* wp = reinterpret_cast<const ulonglong2*>(Dw + (size_t)k * 64 + og4);
        ulonglong2 w0 = __ldg(wp);
        ulonglong2 w1 = __ldg(wp + 1);
        ffma2(acc[0], a, w0.x); ffma2(acc[1], a, w0.y);
        ffma2(acc[2], a, w1.x); ffma2(acc[3], a, w1.y);
    }
}

__device__ __forceinline__ void relu_store(u64t (&acc)[4], float* __restrict__ Ot,
                                           int lane2, int og4) {
#pragma unroll
    for (int o = 0; o < 4; o++) {
        float x0, x1; upk2(acc[o], x0, x1);
        *reinterpret_cast<float2*>(Ot + (og4 + o) * LDA + lane2) =
            make_float2(fmaxf(x0, 0.f), fmaxf(x1, 0.f));
    }
}

// ===================== Kernel A: state encoder + values =====================
__global__ void __launch_bounds__(THREADS) state_kernel(
    const int*   __restrict__ hand_ids,
    const float* __restrict__ dense_state,
    const float* __restrict__ emb_table,
    const float* __restrict__ ln1_g, const float* __restrict__ ln1_b,
    const float* __restrict__ b_card, const float* __restrict__ b_lp,
    const float* __restrict__ b_sn,
    const float* __restrict__ W_ct,   const float* __restrict__ b_ct,
    const float* __restrict__ b_sp,
    const float* __restrict__ ln2_g,  const float* __restrict__ ln2_b,
    const float* __restrict__ bv1,
    const float* __restrict__ Wv2,    const float* __restrict__ bv2,
    float* __restrict__ out_values,
    int B)
{
    __shared__ float Dbuf[52 * LDA];   // dense slice, k-major
    __shared__ float Xb[64 * LDA];     // activation buffer, k-major
    __shared__ float lnet[32 * 56];    // LN'd emb transposed [dim][id]
    __shared__ float ctb[3 * LDA];
    __shared__ float Sbuf[NA], S2buf[NA], Rbuf[NA];
    __shared__ int   sid[NA * 13];

    int tid = threadIdx.x;
    int lane2 = (tid & 31) * 2;
    int og4 = (tid >> 5) * 4;
    long long s0 = (long long)blockIdx.x * NA;
    int ns = (int)(((long long)B - s0) < NA ? ((long long)B - s0) : NA);

    // ---- staging ----
    for (int i = tid; i < ns * 13; i += THREADS) sid[i] = __ldg(hand_ids + s0 * 13 + i);
    for (int i = tid; i < ns * 52; i += THREADS) {       // lp slice rows 0..51
        int s = i / 52, f = i - s * 52;
        Dbuf[f * LDA + s] = __ldg(dense_state + (s0 + s) * 107 + f);
    }
    if (tid < 53) {
        const float4* e4 = reinterpret_cast<const float4*>(emb_table + tid * 32);
        float vals[32]; float s = 0.f, s2 = 0.f;
#pragma unroll
        for (int k = 0; k < 8; k++) {
            float4 f = __ldg(e4 + k);
            vals[4*k] = f.x; vals[4*k+1] = f.y; vals[4*k+2] = f.z; vals[4*k+3] = f.w;
            s += f.x + f.y + f.z + f.w;
            s2 += f.x*f.x + f.y*f.y + f.z*f.z + f.w*f.w;
        }
        float m = s * (1.f/32.f);
        float rv = rsqrtf(s2 * (1.f/32.f) - m*m + 1e-5f);
#pragma unroll
        for (int d = 0; d < 32; d++)
            lnet[d * 56 + tid] = (vals[d] - m) * rv * __ldg(ln1_g + d) + __ldg(ln1_b + d);
    }
    if (tid < NA) { Sbuf[tid] = 0.f; S2buf[tid] = 0.f; Rbuf[tid] = 0.f; }
    __syncthreads();

    // ---- card layer: 13 chunks of K=32 ----
    u64t cacc[4];
    acc_init(cacc, b_card, og4);
    for (int c = 0; c < 13; c++) {
        {   // build chunk: Xb[k][s] = lnemb[k][ id(s,c) ]
            int k = tid >> 4, sb = (tid & 15) * 4;
#pragma unroll
            for (int i = 0; i < 4; i++) {
                int s = sb + i;
                int id = sid[s * 13 + c];
                if ((unsigned)id > 52u) id = 52;
                Xb[k * LDA + s] = lnet[k * 56 + id];
            }
        }
        __syncthreads();
        gemm_k(cacc, Xb, g_wdup + OFF_CARD + (size_t)(c * 32) * 64, 32, lane2, og4);
        __syncthreads();
    }
    relu_store(cacc, Xb, lane2, og4);        // e -> Xb
    __syncthreads();

    // ---- sp accumulates in registers across 4 passes ----
    u64t spacc[4];
    acc_init(spacc, b_sp, og4);
    gemm_k(spacc, Xb, g_wdup + OFF_SP, 64, lane2, og4);          // pass1: e

    u64t acc[4];
    acc_init(acc, b_lp, og4);
    gemm_k(acc, Dbuf, g_wdup + OFF_LP, 52, lane2, og4);          // lp
    __syncthreads();
    relu_store(acc, Xb, lane2, og4);                             // lp -> Xb
    // restage Dbuf with sn rows 52..103, ctb with 104..106
    for (int i = tid; i < ns * 52; i += THREADS) {
        int s = i / 52, f = i - s * 52;
        Dbuf[f * LDA + s] = __ldg(dense_state + (s0 + s) * 107 + 52 + f);
    }
    for (int i = tid; i < ns * 3; i += THREADS) {
        int f = i / NA, s = i - f * NA;
        ctb[f * LDA + s] = __ldg(dense_state + (s0 + s) * 107 + 104 + f);
    }
    __syncthreads();
    gemm_k(spacc, Xb, g_wdup + OFF_SP + 64 * 64, 64, lane2, og4); // pass2: lp
    acc_init(acc, b_sn, og4);
    gemm_k(acc, Dbuf, g_wdup + OFF_SN, 52, lane2, og4);           // sn
    __syncthreads();
    relu_store(acc, Xb, lane2, og4);
    __syncthreads();
    gemm_k(spacc, Xb, g_wdup + OFF_SP + 128 * 64, 64, lane2, og4); // pass3: sn
    __syncthreads();
    {   // ct (3->32) direct into Xb rows 0..31
        int j = tid >> 4, sb = (tid & 15) * 4;
        float w0 = __ldg(W_ct + j), w1 = __ldg(W_ct + 32 + j), w2 = __ldg(W_ct + 64 + j);
        float bj = __ldg(b_ct + j);
#pragma unroll
        for (int i = 0; i < 4; i++) {
            int s = sb + i;
            float v = bj + ctb[s] * w0 + ctb[LDA + s] * w1 + ctb[2 * LDA + s] * w2;
            Xb[j * LDA + s] = fmaxf(v, 0.f);
        }
    }
    __syncthreads();
    gemm_k(spacc, Xb, g_wdup + OFF_SP + 192 * 64, 32, lane2, og4); // pass4: ct

    // ---- relu + LayerNorm (cross-warp smem atomics) ----
    float hv[2][4];
#pragma unroll
    for (int o = 0; o < 4; o++) {
        float x0, x1; upk2(spacc[o], x0, x1);
        hv[0][o] = fmaxf(x0, 0.f); hv[1][o] = fmaxf(x1, 0.f);
    }
#pragma unroll
    for (int c = 0; c < 2; c++) {
        float s = hv[c][0] + hv[c][1] + hv[c][2] + hv[c][3];
        float s2 = hv[c][0]*hv[c][0] + hv[c][1]*hv[c][1] + hv[c][2]*hv[c][2] + hv[c][3]*hv[c][3];
        atomicAdd(&Sbuf[lane2 + c], s);
        atomicAdd(&S2buf[lane2 + c], s2);
    }
    __syncthreads();
    {
        float g[4], be[4];
#pragma unroll
        for (int o = 0; o < 4; o++) { g[o] = __ldg(ln2_g + og4 + o); be[o] = __ldg(ln2_b + og4 + o); }
#pragma unroll
        for (int c = 0; c < 2; c++) {
            float m = Sbuf[lane2 + c] * (1.f/64.f);
            float rv = rsqrtf(S2buf[lane2 + c] * (1.f/64.f) - m * m + 1e-5f);
#pragma unroll
            for (int o = 0; o < 4; o++) hv[c][o] = (hv[c][o] - m) * rv * g[o] + be[o];
        }
#pragma unroll
        for (int o = 0; o < 4; o++)
            *reinterpret_cast<float2*>(Xb + (og4 + o) * LDA + lane2) =
                make_float2(hv[0][o], hv[1][o]);
    }
    __syncthreads();

    {   // write state_h coalesced from Xb
        int tl = tid >> 3, q = tid & 7;
        if (tl < ns) {
            float v[8];
#pragma unroll
            for (int j = 0; j < 8; j++) v[j] = Xb[(q * 8 + j) * LDA + tl];
            float4* dst4 = reinterpret_cast<float4*>(g_state + (s0 + tl) * 64 + q * 8);
            dst4[0] = make_float4(v[0], v[1], v[2], v[3]);
            dst4[1] = make_float4(v[4], v[5], v[6], v[7]);
        }
    }

    // ---- value head ----
    acc_init(acc, bv1, og4);
    gemm_k(acc, Xb, g_wdup + OFF_WV1, 64, lane2, og4);
    {
        float p0 = 0.f, p1 = 0.f;
#pragma unroll
        for (int o = 0; o < 4; o++) {
            float w = __ldg(Wv2 + og4 + o);
            float x0, x1; upk2(acc[o], x0, x1);
            p0 = fmaf(fmaxf(x0, 0.f), w, p0);
            p1 = fmaf(fmaxf(x1, 0.f), w, p1);
        }
        atomicAdd(&Rbuf[lane2 + 0], p0);
        atomicAdd(&Rbuf[lane2 + 1], p1);
    }
    __syncthreads();
    if (tid < ns) out_values[s0 + tid] = Rbuf[tid] + __ldg(bv2);
}

// ===================== Kernel B: action encoder + logits =====================
__global__ void __launch_bounds__(THREADS) action_kernel(
    const float* __restrict__ action_feats,
    const int*   __restrict__ segment_ids,
    const float* __restrict__ ba1, const float* __restrict__ ba2,
    const float* __restrict__ bp1,
    const float* __restrict__ Wp2, const float* __restrict__ bp2,
    float* __restrict__ out_logits,
    int T)
{
    __shared__ float buf1[64 * LDA];   // AFt, later aenc
    __shared__ float buf2[64 * LDA];   // a1, later gathered state
    __shared__ float Rbuf[NA];

    int tid = threadIdx.x;
    int lane2 = (tid & 31) * 2;
    int og4 = (tid >> 5) * 4;
    long long base = (long long)blockIdx.x * NA;
    int nt = (int)(((long long)T - base) < NA ? ((long long)T - base) : NA);

    for (int i = tid; i < nt * 53; i += THREADS) {
        int t = i / 53, f = i - t * 53;
        buf1[f * LDA + t] = __ldg(action_feats + (base + t) * 53 + f);
    }
    if (tid < NA) Rbuf[tid] = 0.f;
    __syncthreads();

    u64t acc[4];
    acc_init(acc, ba1, og4);
    gemm_k(acc, buf1, g_wdup + OFF_WA1, 53, lane2, og4);
    relu_store(acc, buf2, lane2, og4);          // a1 -> buf2
    __syncthreads();

    acc_init(acc, ba2, og4);
    gemm_k(acc, buf2, g_wdup + OFF_WA2, 64, lane2, og4);
    __syncthreads();                            // all warps done reading buf2
    relu_store(acc, buf1, lane2, og4);          // aenc -> buf1
    {   // gather state rows into buf2 (k-major)
        int tl = tid >> 3, q = tid & 7;
        if (tl < nt) {
            int seg = __ldg(segment_ids + base + tl);
            const float4* gs = reinterpret_cast<const float4*>(g_state + (size_t)seg * 64 + q * 8);
            float4 f0 = __ldg(gs), f1 = __ldg(gs + 1);
            int k0 = q * 8;
            buf2[(k0 + 0) * LDA + tl] = f0.x; buf2[(k0 + 1) * LDA + tl] = f0.y;
            buf2[(k0 + 2) * LDA + tl] = f0.z; buf2[(k0 + 3) * LDA + tl] = f0.w;
            buf2[(k0 + 4) * LDA + tl] = f1.x; buf2[(k0 + 5) * LDA + tl] = f1.y;
            buf2[(k0 + 6) * LDA + tl] = f1.z; buf2[(k0 + 7) * LDA + tl] = f1.w;
        }
    }
    __syncthreads();

    acc_init(acc, bp1, og4);
    gemm_k(acc, buf2, g_wdup + OFF_WP1, 64, lane2, og4);           // state part
    gemm_k(acc, buf1, g_wdup + OFF_WP1 + 64 * 64, 64, lane2, og4); // aenc part
    {
        float p0 = 0.f, p1 = 0.f;
#pragma unroll
        for (int o = 0; o < 4; o++) {
            float w = __ldg(Wp2 + og4 + o);
            float x0, x1; upk2(acc[o], x0, x1);
            p0 = fmaf(fmaxf(x0, 0.f), w, p0);
            p1 = fmaf(fmaxf(x1, 0.f), w, p1);
        }
        atomicAdd(&Rbuf[lane2 + 0], p0);
        atomicAdd(&Rbuf[lane2 + 1], p1);
    }
    __syncthreads();
    if (tid < nt) out_logits[base + tid] = Rbuf[tid] + __ldg(bp2);
}

// ===================== launch =====================
extern "C" void kernel_launch(void* const* d_in, const int* in_sizes, int n_in,
                              void* d_out, int out_size) {
    const int*   hand_ids     = (const int*)  d_in[0];
    const float* dense_state  = (const float*)d_in[1];
    const float* action_feats = (const float*)d_in[2];
    const int*   segment_ids  = (const int*)  d_in[3];
    const float* emb_table    = (const float*)d_in[4];
    const float* ln1_g        = (const float*)d_in[5];
    const float* ln1_b        = (const float*)d_in[6];
    const float* W_card       = (const float*)d_in[7];
    const float* b_card       = (const float*)d_in[8];
    const float* W_lp         = (const float*)d_in[9];
    const float* b_lp         = (const float*)d_in[10];
    const float* W_sn         = (const float*)d_in[11];
    const float* b_sn         = (const float*)d_in[12];
    const float* W_ct         = (const float*)d_in[13];
    const float* b_ct         = (const float*)d_in[14];
    const float* W_sp         = (const float*)d_in[15];
    const float* b_sp         = (const float*)d_in[16];
    const float* ln2_g        = (const float*)d_in[17];
    const float* ln2_b        = (const float*)d_in[18];
    const float* Wa1          = (const float*)d_in[19];
    const float* ba1          = (const float*)d_in[20];
    const float* Wa2          = (const float*)d_in[21];
    const float* ba2          = (const float*)d_in[22];
    const float* Wp1          = (const float*)d_in[23];
    const float* bp1          = (const float*)d_in[24];
    const float* Wp2          = (const float*)d_in[25];
    const float* bp2          = (const float*)d_in[26];
    const float* Wv1          = (const float*)d_in[27];
    const float* bv1          = (const float*)d_in[28];
    const float* Wv2          = (const float*)d_in[29];
    const float* bv2          = (const float*)d_in[30];

    int B = in_sizes[0] / 13;
    int T = in_sizes[3];
    float* out = (float*)d_out;   // layout: logits[T] then values[B]

    prep_kernel<<<(NDUP + 255) / 256, 256>>>(W_card, W_lp, W_sn, W_sp, Wv1, Wa1, Wa2, Wp1);

    state_kernel<<<(B + NA - 1) / NA, THREADS>>>(
        hand_ids, dense_state, emb_table, ln1_g, ln1_b,
        b_card, b_lp, b_sn, W_ct, b_ct, b_sp, ln2_g, ln2_b,
        bv1, Wv2, bv2, out + (size_t)T, B);

    action_kernel<<<(T + NA - 1) / NA, THREADS>>>(
        action_feats, segment_ids, ba1, ba2, bp1, Wp2, bp2, out, T);
}

// round 12
// speedup vs baseline: 1.8100x; 1.7519x over previous
#include <cuda_runtime.h>
#include <cstdint>

#define MAXB 262144
__device__ float g_state[(size_t)MAXB * 64];

typedef unsigned long long u64t;

__device__ __forceinline__ u64t pk2(float lo, float hi) {
    u64t r; asm("mov.b64 %0, {%1, %2};" : "=l"(r) : "f"(lo), "f"(hi)); return r;
}
__device__ __forceinline__ void upk2(u64t p, float& lo, float& hi) {
    asm("mov.b64 {%0, %1}, %2;" : "=f"(lo), "=f"(hi) : "l"(p));
}
__device__ __forceinline__ void ffma2(u64t& d, u64t a, u64t b) {
    asm("fma.rn.f32x2 %0, %1, %2, %0;" : "+l"(d) : "l"(a), "l"(b));
}

#define NA      128   // tile rows (actions / samples)
#define LDA     130   // smem row stride, floats (even, ==2 mod 32: low-conflict, 8B-aligned)
#define THREADS 512
// thread mapping: rp = tid & 63 -> rows 2rp, 2rp+1 ; og8 = (tid>>6)*8 -> outputs og8..og8+7
// acc[r][p] = packed (out og8+2p, out og8+2p+1) partial sums for row r.

__device__ __forceinline__ void acc_init(u64t (&acc)[2][4], const float* __restrict__ bias, int og8) {
    ulonglong2 b0 = __ldg(reinterpret_cast<const ulonglong2*>(bias + og8));
    ulonglong2 b1 = __ldg(reinterpret_cast<const ulonglong2*>(bias + og8 + 4));
    acc[0][0] = b0.x; acc[0][1] = b0.y; acc[0][2] = b1.x; acc[0][3] = b1.y;
    acc[1][0] = b0.x; acc[1][1] = b0.y; acc[1][2] = b1.x; acc[1][3] = b1.y;
}

// OUT[128 rows][64 outs] += A_sm(k-major [K][LDA])^T @ W(global row-major [K][64])
__device__ __forceinline__ void gemm2(u64t (&acc)[2][4], const float* __restrict__ As,
                                      const float* __restrict__ Wg, int K,
                                      int rp2, int og8) {
#pragma unroll 4
    for (int k = 0; k < K; k++) {
        float2 av = *reinterpret_cast<const float2*>(As + k * LDA + rp2);
        u64t a0 = pk2(av.x, av.x);
        u64t a1 = pk2(av.y, av.y);
        const ulonglong2* wq = reinterpret_cast<const ulonglong2*>(Wg + (size_t)k * 64 + og8);
        ulonglong2 w0 = __ldg(wq);
        ulonglong2 w1 = __ldg(wq + 1);
        ffma2(acc[0][0], a0, w0.x); ffma2(acc[1][0], a1, w0.x);
        ffma2(acc[0][1], a0, w0.y); ffma2(acc[1][1], a1, w0.y);
        ffma2(acc[0][2], a0, w1.x); ffma2(acc[1][2], a1, w1.x);
        ffma2(acc[0][3], a0, w1.y); ffma2(acc[1][3], a1, w1.y);
    }
}

// relu + store k-major [out][row] for the next layer
__device__ __forceinline__ void relu_store2(u64t (&acc)[2][4], float* __restrict__ Ot,
                                            int rp2, int og8) {
#pragma unroll
    for (int p = 0; p < 4; p++) {
        float e0, o0, e1, o1;
        upk2(acc[0][p], e0, o0);
        upk2(acc[1][p], e1, o1);
        *reinterpret_cast<float2*>(Ot + (og8 + 2 * p) * LDA + rp2) =
            make_float2(fmaxf(e0, 0.f), fmaxf(e1, 0.f));
        *reinterpret_cast<float2*>(Ot + (og8 + 2 * p + 1) * LDA + rp2) =
            make_float2(fmaxf(o0, 0.f), fmaxf(o1, 0.f));
    }
}

// head dot: partial = sum_o relu(acc[r][.]) * w[og8+o], accumulated into Rbuf rows
__device__ __forceinline__ void head_dot(u64t (&acc)[2][4], const float* __restrict__ Wv,
                                         float* __restrict__ Rbuf, int rp2, int og8) {
    ulonglong2 w0 = __ldg(reinterpret_cast<const ulonglong2*>(Wv + og8));
    ulonglong2 w1 = __ldg(reinterpret_cast<const ulonglong2*>(Wv + og8 + 4));
    u64t ws[4] = {w0.x, w0.y, w1.x, w1.y};
    float p0 = 0.f, p1 = 0.f;
#pragma unroll
    for (int p = 0; p < 4; p++) {
        float we, wo; upk2(ws[p], we, wo);
        float e0, o0, e1, o1;
        upk2(acc[0][p], e0, o0);
        upk2(acc[1][p], e1, o1);
        p0 = fmaf(fmaxf(e0, 0.f), we, p0); p0 = fmaf(fmaxf(o0, 0.f), wo, p0);
        p1 = fmaf(fmaxf(e1, 0.f), we, p1); p1 = fmaf(fmaxf(o1, 0.f), wo, p1);
    }
    atomicAdd(&Rbuf[rp2 + 0], p0);
    atomicAdd(&Rbuf[rp2 + 1], p1);
}

// ===================== Kernel A: state encoder + values =====================
__global__ void __launch_bounds__(THREADS) state_kernel(
    const int*   __restrict__ hand_ids,
    const float* __restrict__ dense_state,
    const float* __restrict__ emb_table,
    const float* __restrict__ ln1_g, const float* __restrict__ ln1_b,
    const float* __restrict__ W_card, const float* __restrict__ b_card,
    const float* __restrict__ W_lp,   const float* __restrict__ b_lp,
    const float* __restrict__ W_sn,   const float* __restrict__ b_sn,
    const float* __restrict__ W_ct,   const float* __restrict__ b_ct,
    const float* __restrict__ W_sp,   const float* __restrict__ b_sp,
    const float* __restrict__ ln2_g,  const float* __restrict__ ln2_b,
    const float* __restrict__ Wv1,    const float* __restrict__ bv1,
    const float* __restrict__ Wv2,    const float* __restrict__ bv2,
    float* __restrict__ out_values,
    int B)
{
    __shared__ float Xb[64 * LDA];     // 33.3 KB activation / staging buffer (k-major)
    __shared__ float lnet[32 * 56];    // 7 KB LN'd emb transposed [dim][id]; later aliased as ctb
    __shared__ float Sbuf[NA], S2buf[NA], Rbuf[NA];
    __shared__ int   sid[NA * 13];     // 6.6 KB
    float* ctb = lnet;                 // [3][LDA] alias (card layer done before ct staging)

    int tid = threadIdx.x;
    int rp2 = (tid & 63) * 2;
    int og8 = (tid >> 6) * 8;
    long long s0 = (long long)blockIdx.x * NA;
    int ns = (int)(((long long)B - s0) < NA ? ((long long)B - s0) : NA);

    // ---- staging: hand ids + LN'd embedding table ----
    for (int i = tid; i < ns * 13; i += THREADS) sid[i] = __ldg(hand_ids + s0 * 13 + i);
    if (tid < 53) {
        const float4* e4 = reinterpret_cast<const float4*>(emb_table + tid * 32);
        float vals[32]; float s = 0.f, s2 = 0.f;
#pragma unroll
        for (int k = 0; k < 8; k++) {
            float4 f = __ldg(e4 + k);
            vals[4*k] = f.x; vals[4*k+1] = f.y; vals[4*k+2] = f.z; vals[4*k+3] = f.w;
            s += f.x + f.y + f.z + f.w;
            s2 += f.x*f.x + f.y*f.y + f.z*f.z + f.w*f.w;
        }
        float m = s * (1.f/32.f);
        float rv = rsqrtf(s2 * (1.f/32.f) - m*m + 1e-5f);
#pragma unroll
        for (int d = 0; d < 32; d++)
            lnet[d * 56 + tid] = (vals[d] - m) * rv * __ldg(ln1_g + d) + __ldg(ln1_b + d);
    }
    if (tid < NA) { Sbuf[tid] = 0.f; S2buf[tid] = 0.f; Rbuf[tid] = 0.f; }
    __syncthreads();

    // ---- card layer: 13 chunks of K=32 into register acc ----
    u64t cacc[2][4];
    acc_init(cacc, b_card, og8);
    for (int c = 0; c < 13; c++) {
        {   // build chunk rows 0..31 of Xb: Xb[k][s] = lnemb[k][id(s,c)]
            int k = tid >> 4, sb = (tid & 15) * 8;
#pragma unroll
            for (int i = 0; i < 8; i++) {
                int s = sb + i;
                int id = sid[s * 13 + c];
                if ((unsigned)id > 52u) id = 52;
                Xb[k * LDA + s] = lnet[k * 56 + id];
            }
        }
        __syncthreads();
        gemm2(cacc, Xb, W_card + (size_t)(c * 32) * 64, 32, rp2, og8);
        __syncthreads();
    }
    relu_store2(cacc, Xb, rp2, og8);       // e -> Xb rows 0..63
    __syncthreads();

    // ---- sp accumulates in registers across 4 source passes ----
    u64t spacc[2][4];
    acc_init(spacc, b_sp, og8);
    gemm2(spacc, Xb, W_sp, 64, rp2, og8);                  // pass1: e
    __syncthreads();

    u64t acc[2][4];
    // lp: stage dense[:,0:52] -> Xb rows 0..51
    for (int i = tid; i < ns * 52; i += THREADS) {
        int s = i / 52, f = i - s * 52;
        Xb[f * LDA + s] = __ldg(dense_state + (s0 + s) * 107 + f);
    }
    __syncthreads();
    acc_init(acc, b_lp, og8);
    gemm2(acc, Xb, W_lp, 52, rp2, og8);
    __syncthreads();
    relu_store2(acc, Xb, rp2, og8);                        // lp -> Xb
    __syncthreads();
    gemm2(spacc, Xb, W_sp + 64 * 64, 64, rp2, og8);        // pass2: lp
    __syncthreads();

    // sn: stage dense[:,52:104] -> Xb ; ct inputs -> ctb (alias of lnet)
    for (int i = tid; i < ns * 52; i += THREADS) {
        int s = i / 52, f = i - s * 52;
        Xb[f * LDA + s] = __ldg(dense_state + (s0 + s) * 107 + 52 + f);
    }
    for (int i = tid; i < 3 * NA; i += THREADS) {
        int f = i >> 7, s = i & 127;
        ctb[f * LDA + s] = (s < ns) ? __ldg(dense_state + (s0 + s) * 107 + 104 + f) : 0.f;
    }
    __syncthreads();
    acc_init(acc, b_sn, og8);
    gemm2(acc, Xb, W_sn, 52, rp2, og8);
    __syncthreads();
    relu_store2(acc, Xb, rp2, og8);
    __syncthreads();
    gemm2(spacc, Xb, W_sp + 128 * 64, 64, rp2, og8);       // pass3: sn
    __syncthreads();

    {   // ct (3->32) direct into Xb rows 0..31
        int j = tid >> 4, sb = (tid & 15) * 8;
        float w0 = __ldg(W_ct + j), w1 = __ldg(W_ct + 32 + j), w2 = __ldg(W_ct + 64 + j);
        float bj = __ldg(b_ct + j);
#pragma unroll
        for (int i = 0; i < 8; i++) {
            int s = sb + i;
            float v = bj + ctb[s] * w0 + ctb[LDA + s] * w1 + ctb[2 * LDA + s] * w2;
            Xb[j * LDA + s] = fmaxf(v, 0.f);
        }
    }
    __syncthreads();
    gemm2(spacc, Xb, W_sp + 192 * 64, 32, rp2, og8);       // pass4: ct

    // ---- relu + LayerNorm over 64 outs (cross-group smem atomics) ----
    float h[2][8];
#pragma unroll
    for (int p = 0; p < 4; p++) {
        float e0, o0, e1, o1;
        upk2(spacc[0][p], e0, o0);
        upk2(spacc[1][p], e1, o1);
        h[0][2*p] = fmaxf(e0, 0.f); h[0][2*p+1] = fmaxf(o0, 0.f);
        h[1][2*p] = fmaxf(e1, 0.f); h[1][2*p+1] = fmaxf(o1, 0.f);
    }
#pragma unroll
    for (int r = 0; r < 2; r++) {
        float s = 0.f, s2 = 0.f;
#pragma unroll
        for (int o = 0; o < 8; o++) { s += h[r][o]; s2 += h[r][o] * h[r][o]; }
        atomicAdd(&Sbuf[rp2 + r], s);
        atomicAdd(&S2buf[rp2 + r], s2);
    }
    __syncthreads();
#pragma unroll
    for (int r = 0; r < 2; r++) {
        float m = Sbuf[rp2 + r] * (1.f / 64.f);
        float rv = rsqrtf(S2buf[rp2 + r] * (1.f / 64.f) - m * m + 1e-5f);
#pragma unroll
        for (int o = 0; o < 8; o++)
            h[r][o] = (h[r][o] - m) * rv * __ldg(ln2_g + og8 + o) + __ldg(ln2_b + og8 + o);
    }
#pragma unroll
    for (int o = 0; o < 8; o++)
        *reinterpret_cast<float2*>(Xb + (og8 + o) * LDA + rp2) = make_float2(h[0][o], h[1][o]);
    __syncthreads();

    {   // write state_h coalesced from Xb
        int tl = tid >> 2, q = tid & 3;
        if (tl < ns) {
            float4* dst4 = reinterpret_cast<float4*>(g_state + (s0 + tl) * 64 + q * 16);
#pragma unroll
            for (int j = 0; j < 4; j++) {
                int k0 = q * 16 + j * 4;
                dst4[j] = make_float4(Xb[(k0+0)*LDA + tl], Xb[(k0+1)*LDA + tl],
                                      Xb[(k0+2)*LDA + tl], Xb[(k0+3)*LDA + tl]);
            }
        }
    }

    // ---- value head ----
    acc_init(acc, bv1, og8);
    gemm2(acc, Xb, Wv1, 64, rp2, og8);
    head_dot(acc, Wv2, Rbuf, rp2, og8);
    __syncthreads();
    if (tid < ns) out_values[s0 + tid] = Rbuf[tid] + __ldg(bv2);
}

// ===================== Kernel B: action encoder + logits =====================
__global__ void __launch_bounds__(THREADS) action_kernel(
    const float* __restrict__ action_feats,
    const int*   __restrict__ segment_ids,
    const float* __restrict__ Wa1, const float* __restrict__ ba1,
    const float* __restrict__ Wa2, const float* __restrict__ ba2,
    const float* __restrict__ Wp1, const float* __restrict__ bp1,
    const float* __restrict__ Wp2, const float* __restrict__ bp2,
    float* __restrict__ out_logits,
    int T)
{
    __shared__ float buf[64 * LDA];    // 33.3 KB: AFt -> a1 -> aenc -> gathered state
    __shared__ float Rbuf[NA];

    int tid = threadIdx.x;
    int rp2 = (tid & 63) * 2;
    int og8 = (tid >> 6) * 8;
    long long base = (long long)blockIdx.x * NA;
    int nt = (int)(((long long)T - base) < NA ? ((long long)T - base) : NA);

    for (int i = tid; i < nt * 53; i += THREADS) {
        int t = i / 53, f = i - t * 53;
        buf[f * LDA + t] = __ldg(action_feats + (base + t) * 53 + f);
    }
    if (tid < NA) Rbuf[tid] = 0.f;
    __syncthreads();

    u64t acc[2][4];
    acc_init(acc, ba1, og8);
    gemm2(acc, buf, Wa1, 53, rp2, og8);
    __syncthreads();
    relu_store2(acc, buf, rp2, og8);          // a1 -> buf
    __syncthreads();

    acc_init(acc, ba2, og8);
    gemm2(acc, buf, Wa2, 64, rp2, og8);
    __syncthreads();
    relu_store2(acc, buf, rp2, og8);          // aenc -> buf
    __syncthreads();

    // layer 3: aenc part first (buf holds aenc), then restage buf with state
    acc_init(acc, bp1, og8);
    gemm2(acc, buf, Wp1 + 64 * 64, 64, rp2, og8);   // aenc rows 64..127 of Wp1
    __syncthreads();
    {   // gather state rows into buf (k-major)
        int tl = tid >> 2, q = tid & 3;
        int seg = (tl < nt) ? __ldg(segment_ids + base + tl) : 0;
        const float4* gs = reinterpret_cast<const float4*>(g_state + (size_t)seg * 64 + q * 16);
#pragma unroll
        for (int j = 0; j < 4; j++) {
            float4 f4 = __ldg(gs + j);
            int k0 = q * 16 + j * 4;
            buf[(k0+0)*LDA + tl] = f4.x;
            buf[(k0+1)*LDA + tl] = f4.y;
            buf[(k0+2)*LDA + tl] = f4.z;
            buf[(k0+3)*LDA + tl] = f4.w;
        }
    }
    __syncthreads();
    gemm2(acc, buf, Wp1, 64, rp2, og8);             // state rows 0..63 of Wp1

    head_dot(acc, Wp2, Rbuf, rp2, og8);
    __syncthreads();
    if (tid < nt) out_logits[base + tid] = Rbuf[tid] + __ldg(bp2);
}

// ===================== launch =====================
extern "C" void kernel_launch(void* const* d_in, const int* in_sizes, int n_in,
                              void* d_out, int out_size) {
    const int*   hand_ids     = (const int*)  d_in[0];
    const float* dense_state  = (const float*)d_in[1];
    const float* action_feats = (const float*)d_in[2];
    const int*   segment_ids  = (const int*)  d_in[3];
    const float* emb_table    = (const float*)d_in[4];
    const float* ln1_g        = (const float*)d_in[5];
    const float* ln1_b        = (const float*)d_in[6];
    const float* W_card       = (const float*)d_in[7];
    const float* b_card       = (const float*)d_in[8];
    const float* W_lp         = (const float*)d_in[9];
    const float* b_lp         = (const float*)d_in[10];
    const float* W_sn         = (const float*)d_in[11];
    const float* b_sn         = (const float*)d_in[12];
    const float* W_ct         = (const float*)d_in[13];
    const float* b_ct         = (const float*)d_in[14];
    const float* W_sp         = (const float*)d_in[15];
    const float* b_sp         = (const float*)d_in[16];
    const float* ln2_g        = (const float*)d_in[17];
    const float* ln2_b        = (const float*)d_in[18];
    const float* Wa1          = (const float*)d_in[19];
    const float* ba1          = (const float*)d_in[20];
    const float* Wa2          = (const float*)d_in[21];
    const float* ba2          = (const float*)d_in[22];
    const float* Wp1          = (const float*)d_in[23];
    const float* bp1          = (const float*)d_in[24];
    const float* Wp2          = (const float*)d_in[25];
    const float* bp2          = (const float*)d_in[26];
    const float* Wv1          = (const float*)d_in[27];
    const float* bv1          = (const float*)d_in[28];
    const float* Wv2          = (const float*)d_in[29];
    const float* bv2          = (const float*)d_in[30];

    int B = in_sizes[0] / 13;
    int T = in_sizes[3];
    float* out = (float*)d_out;   // layout: logits[T] then values[B]

    state_kernel<<<(B + NA - 1) / NA, THREADS>>>(
        hand_ids, dense_state, emb_table, ln1_g, ln1_b,
        W_card, b_card, W_lp, b_lp, W_sn, b_sn, W_ct, b_ct,
        W_sp, b_sp, ln2_g, ln2_b, Wv1, bv1, Wv2, bv2,
        out + (size_t)T, B);

    action_kernel<<<(T + NA - 1) / NA, THREADS>>>(
        action_feats, segment_ids, Wa1, ba1, Wa2, ba2,
        Wp1, bp1, Wp2, bp2, out, T);
}

// round 13
// speedup vs baseline: 1.8107x; 1.0004x over previous
#include <cuda_runtime.h>
#include <cstdint>

#define MAXB 262144
__device__ float g_state[(size_t)MAXB * 64];

typedef unsigned long long u64t;

__device__ __forceinline__ u64t pk2(float lo, float hi) {
    u64t r; asm("mov.b64 %0, {%1, %2};" : "=l"(r) : "f"(lo), "f"(hi)); return r;
}
__device__ __forceinline__ void upk2(u64t p, float& lo, float& hi) {
    asm("mov.b64 {%0, %1}, %2;" : "=f"(lo), "=f"(hi) : "l"(p));
}
__device__ __forceinline__ void ffma2(u64t& d, u64t a, u64t b) {
    asm("fma.rn.f32x2 %0, %1, %2, %0;" : "+l"(d) : "l"(a), "l"(b));
}

#define NA      128   // tile rows (actions / samples)
#define LDA     130   // smem row stride, floats (even, ==2 mod 32: low-conflict, 8B-aligned)
#define THREADS 512
// thread mapping: rp = tid & 63 -> rows 2rp, 2rp+1 ; og8 = (tid>>6)*8 -> outputs og8..og8+7
// acc[r][p] = packed (out og8+2p, out og8+2p+1) partial sums for row r.

__device__ __forceinline__ void acc_init(u64t (&acc)[2][4], const float* __restrict__ bias, int og8) {
    ulonglong2 b0 = __ldg(reinterpret_cast<const ulonglong2*>(bias + og8));
    ulonglong2 b1 = __ldg(reinterpret_cast<const ulonglong2*>(bias + og8 + 4));
    acc[0][0] = b0.x; acc[0][1] = b0.y; acc[0][2] = b1.x; acc[0][3] = b1.y;
    acc[1][0] = b0.x; acc[1][1] = b0.y; acc[1][2] = b1.x; acc[1][3] = b1.y;
}

// OUT[128 rows][64 outs] += A_sm(k-major [K][LDA])^T @ W(global row-major [K][64])
__device__ __forceinline__ void gemm2(u64t (&acc)[2][4], const float* __restrict__ As,
                                      const float* __restrict__ Wg, int K,
                                      int rp2, int og8) {
#pragma unroll 4
    for (int k = 0; k < K; k++) {
        float2 av = *reinterpret_cast<const float2*>(As + k * LDA + rp2);
        u64t a0 = pk2(av.x, av.x);
        u64t a1 = pk2(av.y, av.y);
        const ulonglong2* wq = reinterpret_cast<const ulonglong2*>(Wg + (size_t)k * 64 + og8);
        ulonglong2 w0 = __ldg(wq);
        ulonglong2 w1 = __ldg(wq + 1);
        ffma2(acc[0][0], a0, w0.x); ffma2(acc[1][0], a1, w0.x);
        ffma2(acc[0][1], a0, w0.y); ffma2(acc[1][1], a1, w0.y);
        ffma2(acc[0][2], a0, w1.x); ffma2(acc[1][2], a1, w1.x);
        ffma2(acc[0][3], a0, w1.y); ffma2(acc[1][3], a1, w1.y);
    }
}

// relu + store k-major [out][row] for the next layer
__device__ __forceinline__ void relu_store2(u64t (&acc)[2][4], float* __restrict__ Ot,
                                            int rp2, int og8) {
#pragma unroll
    for (int p = 0; p < 4; p++) {
        float e0, o0, e1, o1;
        upk2(acc[0][p], e0, o0);
        upk2(acc[1][p], e1, o1);
        *reinterpret_cast<float2*>(Ot + (og8 + 2 * p) * LDA + rp2) =
            make_float2(fmaxf(e0, 0.f), fmaxf(e1, 0.f));
        *reinterpret_cast<float2*>(Ot + (og8 + 2 * p + 1) * LDA + rp2) =
            make_float2(fmaxf(o0, 0.f), fmaxf(o1, 0.f));
    }
}

// head dot: partial = sum_o relu(acc[r][.]) * w[og8+o], accumulated into Rbuf rows
__device__ __forceinline__ void head_dot(u64t (&acc)[2][4], const float* __restrict__ Wv,
                                         float* __restrict__ Rbuf, int rp2, int og8) {
    ulonglong2 w0 = __ldg(reinterpret_cast<const ulonglong2*>(Wv + og8));
    ulonglong2 w1 = __ldg(reinterpret_cast<const ulonglong2*>(Wv + og8 + 4));
    u64t ws[4] = {w0.x, w0.y, w1.x, w1.y};
    float p0 = 0.f, p1 = 0.f;
#pragma unroll
    for (int p = 0; p < 4; p++) {
        float we, wo; upk2(ws[p], we, wo);
        float e0, o0, e1, o1;
        upk2(acc[0][p], e0, o0);
        upk2(acc[1][p], e1, o1);
        p0 = fmaf(fmaxf(e0, 0.f), we, p0); p0 = fmaf(fmaxf(o0, 0.f), wo, p0);
        p1 = fmaf(fmaxf(e1, 0.f), we, p1); p1 = fmaf(fmaxf(o1, 0.f), wo, p1);
    }
    atomicAdd(&Rbuf[rp2 + 0], p0);
    atomicAdd(&Rbuf[rp2 + 1], p1);
}

// ===================== Kernel A: state encoder + values =====================
__global__ void __launch_bounds__(THREADS) state_kernel(
    const int*   __restrict__ hand_ids,
    const float* __restrict__ dense_state,
    const float* __restrict__ emb_table,
    const float* __restrict__ ln1_g, const float* __restrict__ ln1_b,
    const float* __restrict__ W_card, const float* __restrict__ b_card,
    const float* __restrict__ W_lp,   const float* __restrict__ b_lp,
    const float* __restrict__ W_sn,   const float* __restrict__ b_sn,
    const float* __restrict__ W_ct,   const float* __restrict__ b_ct,
    const float* __restrict__ W_sp,   const float* __restrict__ b_sp,
    const float* __restrict__ ln2_g,  const float* __restrict__ ln2_b,
    const float* __restrict__ Wv1,    const float* __restrict__ bv1,
    const float* __restrict__ Wv2,    const float* __restrict__ bv2,
    float* __restrict__ out_values,
    int B)
{
    __shared__ float Xb[64 * LDA];     // 33.3 KB activation / staging buffer (k-major)
    __shared__ float lnet[32 * 56];    // 7 KB LN'd emb transposed [dim][id]; later aliased as ctb
    __shared__ float Sbuf[NA], S2buf[NA], Rbuf[NA];
    __shared__ int   sid[NA * 13];     // 6.6 KB
    float* ctb = lnet;                 // [3][LDA] alias (card layer done before ct staging)

    int tid = threadIdx.x;
    int rp2 = (tid & 63) * 2;
    int og8 = (tid >> 6) * 8;
    long long s0 = (long long)blockIdx.x * NA;
    int ns = (int)(((long long)B - s0) < NA ? ((long long)B - s0) : NA);

    // ---- staging: hand ids + LN'd embedding table ----
    for (int i = tid; i < ns * 13; i += THREADS) sid[i] = __ldg(hand_ids + s0 * 13 + i);
    if (tid < 53) {
        const float4* e4 = reinterpret_cast<const float4*>(emb_table + tid * 32);
        float vals[32]; float s = 0.f, s2 = 0.f;
#pragma unroll
        for (int k = 0; k < 8; k++) {
            float4 f = __ldg(e4 + k);
            vals[4*k] = f.x; vals[4*k+1] = f.y; vals[4*k+2] = f.z; vals[4*k+3] = f.w;
            s += f.x + f.y + f.z + f.w;
            s2 += f.x*f.x + f.y*f.y + f.z*f.z + f.w*f.w;
        }
        float m = s * (1.f/32.f);
        float rv = rsqrtf(s2 * (1.f/32.f) - m*m + 1e-5f);
#pragma unroll
        for (int d = 0; d < 32; d++)
            lnet[d * 56 + tid] = (vals[d] - m) * rv * __ldg(ln1_g + d) + __ldg(ln1_b + d);
    }
    if (tid < NA) { Sbuf[tid] = 0.f; S2buf[tid] = 0.f; Rbuf[tid] = 0.f; }
    __syncthreads();

    // ---- card layer: 13 chunks of K=32 into register acc ----
    u64t cacc[2][4];
    acc_init(cacc, b_card, og8);
    for (int c = 0; c < 13; c++) {
        {   // build chunk rows 0..31 of Xb: Xb[k][s] = lnemb[k][id(s,c)]
            int k = tid >> 4, sb = (tid & 15) * 8;
#pragma unroll
            for (int i = 0; i < 8; i++) {
                int s = sb + i;
                int id = sid[s * 13 + c];
                if ((unsigned)id > 52u) id = 52;
                Xb[k * LDA + s] = lnet[k * 56 + id];
            }
        }
        __syncthreads();
        gemm2(cacc, Xb, W_card + (size_t)(c * 32) * 64, 32, rp2, og8);
        __syncthreads();
    }
    relu_store2(cacc, Xb, rp2, og8);       // e -> Xb rows 0..63
    __syncthreads();

    // ---- sp accumulates in registers across 4 source passes ----
    u64t spacc[2][4];
    acc_init(spacc, b_sp, og8);
    gemm2(spacc, Xb, W_sp, 64, rp2, og8);                  // pass1: e
    __syncthreads();

    u64t acc[2][4];
    // lp: stage dense[:,0:52] -> Xb rows 0..51
    for (int i = tid; i < ns * 52; i += THREADS) {
        int s = i / 52, f = i - s * 52;
        Xb[f * LDA + s] = __ldg(dense_state + (s0 + s) * 107 + f);
    }
    __syncthreads();
    acc_init(acc, b_lp, og8);
    gemm2(acc, Xb, W_lp, 52, rp2, og8);
    __syncthreads();
    relu_store2(acc, Xb, rp2, og8);                        // lp -> Xb
    __syncthreads();
    gemm2(spacc, Xb, W_sp + 64 * 64, 64, rp2, og8);        // pass2: lp
    __syncthreads();

    // sn: stage dense[:,52:104] -> Xb ; ct inputs -> ctb (alias of lnet)
    for (int i = tid; i < ns * 52; i += THREADS) {
        int s = i / 52, f = i - s * 52;
        Xb[f * LDA + s] = __ldg(dense_state + (s0 + s) * 107 + 52 + f);
    }
    for (int i = tid; i < 3 * NA; i += THREADS) {
        int f = i >> 7, s = i & 127;
        ctb[f * LDA + s] = (s < ns) ? __ldg(dense_state + (s0 + s) * 107 + 104 + f) : 0.f;
    }
    __syncthreads();
    acc_init(acc, b_sn, og8);
    gemm2(acc, Xb, W_sn, 52, rp2, og8);
    __syncthreads();
    relu_store2(acc, Xb, rp2, og8);
    __syncthreads();
    gemm2(spacc, Xb, W_sp + 128 * 64, 64, rp2, og8);       // pass3: sn
    __syncthreads();

    {   // ct (3->32) direct into Xb rows 0..31
        int j = tid >> 4, sb = (tid & 15) * 8;
        float w0 = __ldg(W_ct + j), w1 = __ldg(W_ct + 32 + j), w2 = __ldg(W_ct + 64 + j);
        float bj = __ldg(b_ct + j);
#pragma unroll
        for (int i = 0; i < 8; i++) {
            int s = sb + i;
            float v = bj + ctb[s] * w0 + ctb[LDA + s] * w1 + ctb[2 * LDA + s] * w2;
            Xb[j * LDA + s] = fmaxf(v, 0.f);
        }
    }
    __syncthreads();
    gemm2(spacc, Xb, W_sp + 192 * 64, 32, rp2, og8);       // pass4: ct

    // ---- relu + LayerNorm over 64 outs (cross-group smem atomics) ----
    float h[2][8];
#pragma unroll
    for (int p = 0; p < 4; p++) {
        float e0, o0, e1, o1;
        upk2(spacc[0][p], e0, o0);
        upk2(spacc[1][p], e1, o1);
        h[0][2*p] = fmaxf(e0, 0.f); h[0][2*p+1] = fmaxf(o0, 0.f);
        h[1][2*p] = fmaxf(e1, 0.f); h[1][2*p+1] = fmaxf(o1, 0.f);
    }
#pragma unroll
    for (int r = 0; r < 2; r++) {
        float s = 0.f, s2 = 0.f;
#pragma unroll
        for (int o = 0; o < 8; o++) { s += h[r][o]; s2 += h[r][o] * h[r][o]; }
        atomicAdd(&Sbuf[rp2 + r], s);
        atomicAdd(&S2buf[rp2 + r], s2);
    }
    __syncthreads();
#pragma unroll
    for (int r = 0; r < 2; r++) {
        float m = Sbuf[rp2 + r] * (1.f / 64.f);
        float rv = rsqrtf(S2buf[rp2 + r] * (1.f / 64.f) - m * m + 1e-5f);
#pragma unroll
        for (int o = 0; o < 8; o++)
            h[r][o] = (h[r][o] - m) * rv * __ldg(ln2_g + og8 + o) + __ldg(ln2_b + og8 + o);
    }
#pragma unroll
    for (int o = 0; o < 8; o++)
        *reinterpret_cast<float2*>(Xb + (og8 + o) * LDA + rp2) = make_float2(h[0][o], h[1][o]);
    __syncthreads();

    {   // write state_h coalesced from Xb
        int tl = tid >> 2, q = tid & 3;
        if (tl < ns) {
            float4* dst4 = reinterpret_cast<float4*>(g_state + (s0 + tl) * 64 + q * 16);
#pragma unroll
            for (int j = 0; j < 4; j++) {
                int k0 = q * 16 + j * 4;
                dst4[j] = make_float4(Xb[(k0+0)*LDA + tl], Xb[(k0+1)*LDA + tl],
                                      Xb[(k0+2)*LDA + tl], Xb[(k0+3)*LDA + tl]);
            }
        }
    }

    // ---- value head ----
    acc_init(acc, bv1, og8);
    gemm2(acc, Xb, Wv1, 64, rp2, og8);
    head_dot(acc, Wv2, Rbuf, rp2, og8);
    __syncthreads();
    if (tid < ns) out_values[s0 + tid] = Rbuf[tid] + __ldg(bv2);
}

// ===================== Kernel B: action encoder + logits =====================
__global__ void __launch_bounds__(THREADS) action_kernel(
    const float* __restrict__ action_feats,
    const int*   __restrict__ segment_ids,
    const float* __restrict__ Wa1, const float* __restrict__ ba1,
    const float* __restrict__ Wa2, const float* __restrict__ ba2,
    const float* __restrict__ Wp1, const float* __restrict__ bp1,
    const float* __restrict__ Wp2, const float* __restrict__ bp2,
    float* __restrict__ out_logits,
    int T)
{
    __shared__ float buf[64 * LDA];    // 33.3 KB: AFt -> a1 -> aenc -> gathered state
    __shared__ float Rbuf[NA];

    int tid = threadIdx.x;
    int rp2 = (tid & 63) * 2;
    int og8 = (tid >> 6) * 8;
    long long base = (long long)blockIdx.x * NA;
    int nt = (int)(((long long)T - base) < NA ? ((long long)T - base) : NA);

    for (int i = tid; i < nt * 53; i += THREADS) {
        int t = i / 53, f = i - t * 53;
        buf[f * LDA + t] = __ldg(action_feats + (base + t) * 53 + f);
    }
    if (tid < NA) Rbuf[tid] = 0.f;
    __syncthreads();

    u64t acc[2][4];
    acc_init(acc, ba1, og8);
    gemm2(acc, buf, Wa1, 53, rp2, og8);
    __syncthreads();
    relu_store2(acc, buf, rp2, og8);          // a1 -> buf
    __syncthreads();

    acc_init(acc, ba2, og8);
    gemm2(acc, buf, Wa2, 64, rp2, og8);
    __syncthreads();
    relu_store2(acc, buf, rp2, og8);          // aenc -> buf
    __syncthreads();

    // layer 3: aenc part first (buf holds aenc), then restage buf with state
    acc_init(acc, bp1, og8);
    gemm2(acc, buf, Wp1 + 64 * 64, 64, rp2, og8);   // aenc rows 64..127 of Wp1
    __syncthreads();
    {   // gather state rows into buf (k-major)
        int tl = tid >> 2, q = tid & 3;
        int seg = (tl < nt) ? __ldg(segment_ids + base + tl) : 0;
        const float4* gs = reinterpret_cast<const float4*>(g_state + (size_t)seg * 64 + q * 16);
#pragma unroll
        for (int j = 0; j < 4; j++) {
            float4 f4 = __ldg(gs + j);
            int k0 = q * 16 + j * 4;
            buf[(k0+0)*LDA + tl] = f4.x;
            buf[(k0+1)*LDA + tl] = f4.y;
            buf[(k0+2)*LDA + tl] = f4.z;
            buf[(k0+3)*LDA + tl] = f4.w;
        }
    }
    __syncthreads();
    gemm2(acc, buf, Wp1, 64, rp2, og8);             // state rows 0..63 of Wp1

    head_dot(acc, Wp2, Rbuf, rp2, og8);
    __syncthreads();
    if (tid < nt) out_logits[base + tid] = Rbuf[tid] + __ldg(bp2);
}

// ===================== launch =====================
extern "C" void kernel_launch(void* const* d_in, const int* in_sizes, int n_in,
                              void* d_out, int out_size) {
    const int*   hand_ids     = (const int*)  d_in[0];
    const float* dense_state  = (const float*)d_in[1];
    const float* action_feats = (const float*)d_in[2];
    const int*   segment_ids  = (const int*)  d_in[3];
    const float* emb_table    = (const float*)d_in[4];
    const float* ln1_g        = (const float*)d_in[5];
    const float* ln1_b        = (const float*)d_in[6];
    const float* W_card       = (const float*)d_in[7];
    const float* b_card       = (const float*)d_in[8];
    const float* W_lp         = (const float*)d_in[9];
    const float* b_lp         = (const float*)d_in[10];
    const float* W_sn         = (const float*)d_in[11];
    const float* b_sn         = (const float*)d_in[12];
    const float* W_ct         = (const float*)d_in[13];
    const float* b_ct         = (const float*)d_in[14];
    const float* W_sp         = (const float*)d_in[15];
    const float* b_sp         = (const float*)d_in[16];
    const float* ln2_g        = (const float*)d_in[17];
    const float* ln2_b        = (const float*)d_in[18];
    const float* Wa1          = (const float*)d_in[19];
    const float* ba1          = (const float*)d_in[20];
    const float* Wa2          = (const float*)d_in[21];
    const float* ba2          = (const float*)d_in[22];
    const float* Wp1          = (const float*)d_in[23];
    const float* bp1          = (const float*)d_in[24];
    const float* Wp2          = (const float*)d_in[25];
    const float* bp2          = (const float*)d_in[26];
    const float* Wv1          = (const float*)d_in[27];
    const float* bv1          = (const float*)d_in[28];
    const float* Wv2          = (const float*)d_in[29];
    const float* bv2          = (const float*)d_in[30];

    int B = in_sizes[0] / 13;
    int T = in_sizes[3];
    float* out = (float*)d_out;   // layout: logits[T] then values[B]

    state_kernel<<<(B + NA - 1) / NA, THREADS>>>(
        hand_ids, dense_state, emb_table, ln1_g, ln1_b,
        W_card, b_card, W_lp, b_lp, W_sn, b_sn, W_ct, b_ct,
        W_sp, b_sp, ln2_g, ln2_b, Wv1, bv1, Wv2, bv2,
        out + (size_t)T, B);

    action_kernel<<<(T + NA - 1) / NA, THREADS>>>(
        action_feats, segment_ids, Wa1, ba1, Wa2, ba2,
        Wp1, bp1, Wp2, bp2, out, T);
}